// round 7
// baseline (speedup 1.0000x reference)
#include <cuda_runtime.h>
#include <cuda_bf16.h>
#include <math.h>

// Shapes (fixed by the problem)
#define BATCH 16
#define CHAN  256
#define HH_   224
#define WW_   224
#define PLANE_ELEMS (HH_ * WW_)          // 50176 floats per plane
#define PLANE_V4    (PLANE_ELEMS / 4)    // 12544 float4 per plane
#define NPLANES     (BATCH * CHAN)       // 4096
#define W4_PER_ROW  (WW_ / 4)            // 56 float4 per row
#define SUB_ELEMS   (112 * 112)

#define NBLOCKS 148
#define NTHREADS 1024
#define GROUP 7                           // planes per deferred-reduction group

// dynamic smem: plane cache (200704 B) + scratch region (14336 B)
#define CACHE_BYTES   (PLANE_V4 * 16)     // 200704
#define SCRATCH_FLOATS 3584               // 14336 B
#define SMEM_DYN      (CACHE_BYTES + SCRATCH_FLOATS * 4)

// Scratch globals (no allocation allowed)
__device__ float    g_sums[NPLANES * 4];
__device__ unsigned g_arrive;             // monotonic grid-barrier counter

__global__ __launch_bounds__(NTHREADS, 1)
void fused_kernel(const float* __restrict__ x, float* __restrict__ out,
                  const float* __restrict__ w1, const float* __restrict__ w2,
                  const float* __restrict__ w_enc) {
    extern __shared__ char smem_raw[];
    float4* cache = (float4*)smem_raw;                       // last-plane cache
    float*  scr   = (float*)(smem_raw + CACHE_BYTES);        // scratch region

    const int bid = blockIdx.x;
    const int t   = threadIdx.x;
    const int lane = t & 31, wid = t >> 5;                   // 32 warps

    // plane partition: blocks 0..99 get 28 planes, 100..147 get 27
    const int p0 = bid * 27 + min(bid, 100);
    const int np = 27 + (bid < 100);

    const float4* __restrict__ xv = (const float4*)x;
    float4* __restrict__ ov = (float4*)out;

    // ---------------- Phase 1: parity sums (forward plane order) ----------
    // scratch as red[GROUP][32][4]
    float* red = scr;
    for (int pl = 0; pl < np; ++pl) {
        const int plane = p0 + pl;
        const float4* __restrict__ p = xv + (size_t)plane * PLANE_V4;
        const bool cache_this = (pl == np - 1);

        float a0 = 0.f, a1 = 0.f, a2 = 0.f, a3 = 0.f;
        for (int i = t; i < PLANE_V4; i += NTHREADS) {
            float4 v = p[i];
            if (cache_this) cache[i] = v;
            int h = i / W4_PER_ROW;
            float ev = v.x + v.z;
            float od = v.y + v.w;
            if (h & 1) { a1 += ev; a3 += od; }
            else       { a0 += ev; a2 += od; }
        }
        // warp reduce
        #pragma unroll
        for (int off = 16; off > 0; off >>= 1) {
            a0 += __shfl_down_sync(0xffffffffu, a0, off);
            a1 += __shfl_down_sync(0xffffffffu, a1, off);
            a2 += __shfl_down_sync(0xffffffffu, a2, off);
            a3 += __shfl_down_sync(0xffffffffu, a3, off);
        }
        int r = pl % GROUP;
        if (lane == 0) {
            float* dst = red + ((r * 32) + wid) * 4;
            dst[0] = a0; dst[1] = a1; dst[2] = a2; dst[3] = a3;
        }
        // flush group
        if (r == GROUP - 1 || pl == np - 1) {
            __syncthreads();
            int nflush = r + 1;
            if (t < nflush * 4) {
                int plx = t >> 2, k = t & 3;
                float s = 0.f;
                #pragma unroll
                for (int w = 0; w < 32; w++) s += red[((plx * 32) + w) * 4 + k];
                g_sums[(size_t)(p0 + (pl - r) + plx) * 4 + k] = s;
            }
            __syncthreads();
        }
    }

    // ---------------- Grid barrier (monotonic counter) --------------------
    if (t == 0) {
        __threadfence();
        unsigned old = atomicAdd(&g_arrive, 1u);
        unsigned target = (old / NBLOCKS + 1u) * NBLOCKS;
        while (atomicAdd(&g_arrive, 0u) < target) { }
        __threadfence();
    }
    __syncthreads();

    // ---------------- Phase 2: head for this block's batch(es) ------------
    // scratch layout (floats): ori[2][4][256]=2048, ysh[2][256]=512,
    // hsh[2][128]=256, rr[2][8][4]=64, scpl[28], itop[2]
    float* ori  = scr;                 // [slice][band][chan]
    float* ysh  = scr + 2048;          // [slice][chan]
    float* hsh  = scr + 2048 + 512;    // [slice][128]
    float* rr   = scr + 2048 + 512 + 256;          // [slice][8][4]
    float* scpl = scr + 2048 + 512 + 256 + 64;     // [28]
    int*   itop = (int*)(scr + 2048 + 512 + 256 + 64 + 28);

    const int b_first = p0 >> 8;
    const int b_last  = (p0 + np - 1) >> 8;
    const int nb      = b_last - b_first + 1;      // 1 or 2

    const int slice = t >> 8;          // 0..3
    const int c     = t & 255;
    const bool act  = (slice < nb);
    const int wid_l = (t >> 5) & 7;    // warp within slice

    float LL = 0.f, HL = 0.f, LH = 0.f, HHb = 0.f;
    if (act) {
        const float inv = 0.5f / (float)SUB_ELEMS;
        const size_t gi = ((size_t)(b_first + slice) * CHAN + c) * 4;
        float m1 = g_sums[gi + 0] * inv;
        float m2 = g_sums[gi + 1] * inv;
        float m3 = g_sums[gi + 2] * inv;
        float m4 = g_sums[gi + 3] * inv;
        LL  =  m1 + m2 + m3 + m4;
        HL  = -m1 - m2 + m3 + m4;
        LH  = -m1 + m2 - m3 + m4;
        HHb =  m1 - m2 - m3 + m4;
        ori[(slice * 4 + 0) * CHAN + c] = LL;
        ori[(slice * 4 + 1) * CHAN + c] = HL;
        ori[(slice * 4 + 2) * CHAN + c] = LH;
        ori[(slice * 4 + 3) * CHAN + c] = HHb;

        float we = w_enc[c];
        float q0 = LL * we, q1 = HL * we, q2 = LH * we, q3 = HHb * we;
        #pragma unroll
        for (int off = 16; off > 0; off >>= 1) {
            q0 += __shfl_down_sync(0xffffffffu, q0, off);
            q1 += __shfl_down_sync(0xffffffffu, q1, off);
            q2 += __shfl_down_sync(0xffffffffu, q2, off);
            q3 += __shfl_down_sync(0xffffffffu, q3, off);
        }
        if (lane == 0) {
            float* d = rr + (slice * 8 + wid_l) * 4;
            d[0] = q0; d[1] = q1; d[2] = q2; d[3] = q3;
        }
    }
    __syncthreads();
    if (act && c == 0) {
        float l0 = 0.f, l1 = 0.f, l2 = 0.f, l3 = 0.f;
        #pragma unroll
        for (int w = 0; w < 8; w++) {
            float* d = rr + (slice * 8 + w) * 4;
            l0 += d[0]; l1 += d[1]; l2 += d[2]; l3 += d[3];
        }
        int best = 0; float bv = l0;
        if (l1 > bv) { bv = l1; best = 1; }
        if (l2 > bv) { bv = l2; best = 2; }
        if (l3 > bv) { bv = l3; best = 3; }
        itop[slice] = best;
    }
    __syncthreads();
    if (act) {
        float Q = ori[(slice * 4 + itop[slice]) * CHAN + c];
        ysh[slice * CHAN + c] = fmaxf(LL - Q, 0.f) + fmaxf(HL - Q, 0.f)
                              + fmaxf(LH - Q, 0.f) + fmaxf(HHb - Q, 0.f);
    }
    __syncthreads();
    // h = relu(y @ w1^T): 128 outputs per active slice
    if (act && c < 128) {
        const float* __restrict__ row = w1 + (size_t)c * CHAN;
        const float* __restrict__ yv = ysh + slice * CHAN;
        float acc = 0.f;
        #pragma unroll 8
        for (int k = 0; k < CHAN; k++) acc = fmaf(yv[k], row[k], acc);
        hsh[slice * 128 + c] = fmaxf(acc, 0.f);
    }
    __syncthreads();
    // scale for each owned plane: sigmoid(h[batch] . w2_row[channel])
    if (t < np) {
        const int plane = p0 + t;
        const int bb = (plane >> 8) - b_first;
        const int ch = plane & 255;
        const float* __restrict__ row = w2 + (size_t)ch * 128;
        const float* __restrict__ hv = hsh + bb * 128;
        float acc = 0.f;
        #pragma unroll 8
        for (int k = 0; k < 128; k++) acc = fmaf(hv[k], row[k], acc);
        scpl[t] = 1.0f / (1.0f + __expf(-acc));
    }
    __syncthreads();

    // ---------------- Phase 3: out = x * s (reverse plane order) ----------
    {   // last plane from smem cache
        const int pl = np - 1;
        const int plane = p0 + pl;
        const float s = scpl[pl];
        float4* __restrict__ dst = ov + (size_t)plane * PLANE_V4;
        for (int i = t; i < PLANE_V4; i += NTHREADS) {
            float4 v = cache[i];
            v.x *= s; v.y *= s; v.z *= s; v.w *= s;
            __stcs(&dst[i], v);
        }
    }
    for (int pl = np - 2; pl >= 0; --pl) {
        const int plane = p0 + pl;
        const float s = scpl[pl];
        const float4* __restrict__ src = xv + (size_t)plane * PLANE_V4;
        float4* __restrict__ dst = ov + (size_t)plane * PLANE_V4;
        for (int i = t; i < PLANE_V4; i += NTHREADS) {
            float4 v = src[i];
            v.x *= s; v.y *= s; v.z *= s; v.w *= s;
            __stcs(&dst[i], v);
        }
    }
}

// ---------------------------------------------------------------------------
extern "C" void kernel_launch(void* const* d_in, const int* in_sizes, int n_in,
                              void* d_out, int out_size) {
    const float* x     = (const float*)d_in[0];  // [16,256,224,224]
    const float* w1    = (const float*)d_in[1];  // [128,256]
    const float* w2    = (const float*)d_in[2];  // [256,128]
    const float* w_enc = (const float*)d_in[3];  // [1,256]
    float* out = (float*)d_out;

    cudaFuncSetAttribute(fused_kernel,
                         cudaFuncAttributeMaxDynamicSharedMemorySize, SMEM_DYN);
    fused_kernel<<<NBLOCKS, NTHREADS, SMEM_DYN>>>(x, out, w1, w2, w_enc);
}